// round 14
// baseline (speedup 1.0000x reference)
#include <cuda_runtime.h>
#include <cuda_fp16.h>

// IVPLoss: 8-step Euler trajectories of bilinear-sampled vector fields,
// MSE between pred and true trajectories (incl. identity step 0).
//
// R14 = R9 kernel bodies, two-chunk fork/join pipeline:
//   capture stream: repack(b=0..3) -> evA -> repack(b=4..7) -> evB
//   s2:             wait evA -> traj(0..3) -> wait evB -> traj(4..7)
// repack(4..7) overlaps traj(0..3). Chunks of 4 batches keep traj
// launches at 9216 blocks (~7.8 waves) so they retain monolithic L1
// efficiency — R13's 8-way split (2-wave grids, 8 events) lost 2x more
// to tails/sync than overlap gained.
//
// Packed layout per pixel (8B): { half2(c0[x],c1[x]), half2(c0[x+1],c1[x+1]) }
// padded col 768 = col 767, padded row 768 = row 767 ->
// one bilinear sample = 2 coalesced LDG.64 + HFMA2 lerps, no y+1 clamp.

#define Bv 8
#define Hv 768
#define Wv 768
#define WPK 769
#define HPK 769
#define NSTEPS 8
#define DXC 0.5f
#define HALFB 4                       // batches per chunk

#define PLANE (Hv * Wv)               // 589824
#define PK_PLANE (HPK * WPK)          // 591361
#define PK_TOTAL (Bv * PK_PLANE)

#define RP_BLKS ((PK_PLANE + 255) / 256)   // 2311

__device__ uint2 g_pred[PK_TOTAL];
__device__ uint2 g_true[PK_TOTAL];
__device__ double g_acc;

__device__ __forceinline__ unsigned int h2u(__half2 h) {
    return *reinterpret_cast<unsigned int*>(&h);
}

__device__ __forceinline__ uint2 pack_pair(const float* __restrict__ f,
                                           int base, int xs, int x1) {
    __half2 p0 = __floats2half2_rn(__ldg(f + base + xs),
                                   __ldg(f + base + PLANE + xs));
    __half2 p1 = __floats2half2_rn(__ldg(f + base + x1),
                                   __ldg(f + base + PLANE + x1));
    return make_uint2(h2u(p0), h2u(p1));
}

// repack chunk: grid (RP_BLKS, HALFB); batch = b0 + blockIdx.y
__global__ __launch_bounds__(256) void repack_kernel(const float* __restrict__ pred,
                                                     const float* __restrict__ tru,
                                                     int b0) {
    int idx = blockIdx.x * blockDim.x + threadIdx.x;   // element within batch
    int b = b0 + blockIdx.y;
    if (idx == 0 && b == 0) g_acc = 0.0;               // reset before any traj
    if (idx >= PK_PLANE) return;
    int x = idx % WPK;
    int y = idx / WPK;
    int xs = min(x, Wv - 1);                 // padded col duplicates last col
    int x1 = min(xs + 1, Wv - 1);
    int ys = min(y, Hv - 1);                 // padded row duplicates last row
    int base = b * 2 * PLANE + ys * Wv;      // channel-0 row base
    int dst = b * PK_PLANE + idx;
    g_pred[dst] = pack_pair(pred, base, xs, x1);
    g_true[dst] = pack_pair(tru,  base, xs, x1);
}

__device__ __forceinline__ float2 bsample(const uint2* __restrict__ P,
                                          float x, float y) {
    // clip to [0, W-1] / [0, H-1] (matches jnp.clip)
    x = fminf(fmaxf(x, 0.0f), (float)(Wv - 1));
    y = fminf(fmaxf(y, 0.0f), (float)(Hv - 1));
    float xf = floorf(x);
    float yf = floorf(y);
    int xi = (int)xf;
    int yi = (int)yf;
    __half2 wx2 = __float2half2_rn(x - xf);
    __half2 wy2 = __float2half2_rn(y - yf);

    int ofs = yi * WPK + xi;
    uint2 r0 = __ldg(P + ofs);
    uint2 r1 = __ldg(P + ofs + WPK);    // padded bottom row: always valid
    __half2 v00 = *reinterpret_cast<__half2*>(&r0.x);
    __half2 v01 = *reinterpret_cast<__half2*>(&r0.y);
    __half2 v10 = *reinterpret_cast<__half2*>(&r1.x);
    __half2 v11 = *reinterpret_cast<__half2*>(&r1.y);

    __half2 top = __hfma2(wx2, __hsub2(v01, v00), v00);
    __half2 bot = __hfma2(wx2, __hsub2(v11, v10), v10);
    __half2 res = __hfma2(wy2, __hsub2(bot, top), top);
    return __half22float2(res);
}

// traj chunk: grid (3, 768, HALFB); batch = b0 + blockIdx.z
__global__ __launch_bounds__(256) void traj_kernel(int b0) {
    int x = blockIdx.x * blockDim.x + threadIdx.x;  // 0..767
    int y = blockIdx.y;
    int b = b0 + blockIdx.z;
    const uint2* __restrict__ Pp = g_pred + b * PK_PLANE;
    const uint2* __restrict__ Pt = g_true + b * PK_PLANE;

    float pxp = (float)x, pyp = (float)y;   // pred trajectory
    float pxt = (float)x, pyt = (float)y;   // true trajectory
    float acc = 0.0f;

    #pragma unroll
    for (int s = 0; s < NSTEPS; s++) {
        float2 vp = bsample(Pp, pxp, pyp);
        float2 vt = bsample(Pt, pxt, pyt);
        pxp = fmaf(DXC, vp.x, pxp);
        pyp = fmaf(DXC, vp.y, pyp);
        pxt = fmaf(DXC, vt.x, pxt);
        pyt = fmaf(DXC, vt.y, pyt);
        float dx = pxt - pxp;
        float dy = pyt - pyp;
        acc = fmaf(dx, dx, acc);
        acc = fmaf(dy, dy, acc);
    }

    // block reduction: warp shuffle -> shared -> warp0 -> atomicAdd(double)
    float v = acc;
    #pragma unroll
    for (int o = 16; o > 0; o >>= 1)
        v += __shfl_down_sync(0xffffffffu, v, o);

    __shared__ float sred[8];
    int lane = threadIdx.x & 31;
    int wid  = threadIdx.x >> 5;
    if (lane == 0) sred[wid] = v;
    __syncthreads();
    if (wid == 0) {
        v = (lane < 8) ? sred[lane] : 0.0f;
        #pragma unroll
        for (int o = 4; o > 0; o >>= 1)
            v += __shfl_down_sync(0xffffffffu, v, o);
        if (lane == 0) atomicAdd(&g_acc, (double)v);
    }
}

__global__ void finalize_kernel(float* __restrict__ out) {
    const double cnt = (double)(NSTEPS + 1) * Bv * 2 * Hv * Wv;  // 84934656
    *out = (float)(g_acc / cnt);
}

extern "C" void kernel_launch(void* const* d_in, const int* in_sizes, int n_in,
                              void* d_out, int out_size) {
    const float* vf_pred = (const float*)d_in[0];
    const float* vf_true = (const float*)d_in[1];
    float* out = (float*)d_out;

    // two-chunk fork/join pipeline (host-side stream/event objects only —
    // no device memory; created per host invocation, not destroyed because
    // destruction during an active capture is illegal).
    cudaStream_t s2;
    cudaStreamCreateWithFlags(&s2, cudaStreamNonBlocking);
    cudaEvent_t evFork, evA, evB, evJoin;
    cudaEventCreateWithFlags(&evFork, cudaEventDisableTiming);
    cudaEventCreateWithFlags(&evA,   cudaEventDisableTiming);
    cudaEventCreateWithFlags(&evB,   cudaEventDisableTiming);
    cudaEventCreateWithFlags(&evJoin, cudaEventDisableTiming);

    cudaEventRecord(evFork, 0);
    cudaStreamWaitEvent(s2, evFork, 0);           // fork s2 from capture stream

    dim3 rp_grid(RP_BLKS, HALFB);
    dim3 tj_grid(Wv / 256, Hv, HALFB);

    repack_kernel<<<rp_grid, 256>>>(vf_pred, vf_true, 0);
    cudaEventRecord(evA, 0);
    repack_kernel<<<rp_grid, 256>>>(vf_pred, vf_true, HALFB);
    cudaEventRecord(evB, 0);

    cudaStreamWaitEvent(s2, evA, 0);
    traj_kernel<<<tj_grid, 256, 0, s2>>>(0);      // overlaps repack(4..7)
    cudaStreamWaitEvent(s2, evB, 0);
    traj_kernel<<<tj_grid, 256, 0, s2>>>(HALFB);

    cudaEventRecord(evJoin, s2);
    cudaStreamWaitEvent(0, evJoin, 0);            // join s2 back
    finalize_kernel<<<1, 1>>>(out);
}

// round 15
// speedup vs baseline: 1.3565x; 1.3565x over previous
#include <cuda_runtime.h>
#include <cuda_fp16.h>

// IVPLoss: 8-step Euler trajectories of bilinear-sampled vector fields,
// MSE between pred and true trajectories (incl. identity step 0).
//
// R15 = R9 (best: 115.3us) + 2D warp tiling in traj:
//  each warp owns an 8-wide x 4-tall pixel tile (x = lane%8, y = lane/8)
//  instead of a 32x1 strip. Per distinct row the warp's x-span is 8
//  elements = 64B = ONE 128B line (was 256B = 2+ lines), cutting L1
//  wavefronts/request ~30% — traj's binding resource (L1 85%).
//  Single stream (R12-R14 proved stream overlap contends on per-SM L1).
//  repack: R2/R9 per-pixel gather (closed at ~24us), padded row+col.
//
// Packed layout per pixel (8B): { half2(c0[x],c1[x]), half2(c0[x+1],c1[x+1]) }
// -> one bilinear sample = 2 LDG.64 + HFMA2 lerps, no y+1 clamp.

#define Bv 8
#define Hv 768
#define Wv 768
#define WPK 769                      // padded width  (col 768 = col 767)
#define HPK 769                      // padded height (row 768 = row 767)
#define NSTEPS 8
#define DXC 0.5f

#define PLANE (Hv * Wv)              // 589824
#define PK_PLANE (HPK * WPK)         // 591361
#define PK_TOTAL (Bv * PK_PLANE)     // 4730888

__device__ uint2 g_pred[PK_TOTAL];
__device__ uint2 g_true[PK_TOTAL];
__device__ double g_acc;

__device__ __forceinline__ unsigned int h2u(__half2 h) {
    return *reinterpret_cast<unsigned int*>(&h);
}

__device__ __forceinline__ uint2 pack_pair(const float* __restrict__ f,
                                           int base, int xs, int x1) {
    __half2 p0 = __floats2half2_rn(__ldg(f + base + xs),
                                   __ldg(f + base + PLANE + xs));
    __half2 p1 = __floats2half2_rn(__ldg(f + base + x1),
                                   __ldg(f + base + PLANE + x1));
    return make_uint2(h2u(p0), h2u(p1));
}

// one thread per packed element (R2 structure; best measured repack)
__global__ __launch_bounds__(256) void repack_kernel(const float* __restrict__ pred,
                                                     const float* __restrict__ tru) {
    int idx = blockIdx.x * blockDim.x + threadIdx.x;
    if (idx == 0) g_acc = 0.0;
    if (idx >= PK_TOTAL) return;
    int x = idx % WPK;
    int rest = idx / WPK;
    int y = rest % HPK;
    int b = rest / HPK;
    int xs = min(x, Wv - 1);                 // padded col duplicates last col
    int x1 = min(xs + 1, Wv - 1);
    int ys = min(y, Hv - 1);                 // padded row duplicates last row
    int base = b * 2 * PLANE + ys * Wv;      // channel-0 row base
    g_pred[idx] = pack_pair(pred, base, xs, x1);
    g_true[idx] = pack_pair(tru,  base, xs, x1);
}

__device__ __forceinline__ float2 bsample(const uint2* __restrict__ P,
                                          float x, float y) {
    // clip to [0, W-1] / [0, H-1] (matches jnp.clip)
    x = fminf(fmaxf(x, 0.0f), (float)(Wv - 1));
    y = fminf(fmaxf(y, 0.0f), (float)(Hv - 1));
    float xf = floorf(x);
    float yf = floorf(y);
    int xi = (int)xf;
    int yi = (int)yf;
    __half2 wx2 = __float2half2_rn(x - xf);
    __half2 wy2 = __float2half2_rn(y - yf);

    int ofs = yi * WPK + xi;
    uint2 r0 = __ldg(P + ofs);
    uint2 r1 = __ldg(P + ofs + WPK);    // padded bottom row: always valid
    __half2 v00 = *reinterpret_cast<__half2*>(&r0.x);
    __half2 v01 = *reinterpret_cast<__half2*>(&r0.y);
    __half2 v10 = *reinterpret_cast<__half2*>(&r1.x);
    __half2 v11 = *reinterpret_cast<__half2*>(&r1.y);

    __half2 top = __hfma2(wx2, __hsub2(v01, v00), v00);
    __half2 bot = __hfma2(wx2, __hsub2(v11, v10), v10);
    __half2 res = __hfma2(wy2, __hsub2(bot, top), top);
    return __half22float2(res);
}

// grid (96, 24, 8), block 256: warp = 8x4 pixel tile, block = 8x32 tile
__global__ __launch_bounds__(256) void traj_kernel() {
    int tid = threadIdx.x;
    int x = blockIdx.x * 8  + (tid & 7);   // 0..767
    int y = blockIdx.y * 32 + (tid >> 3);  // 0..767
    int b = blockIdx.z;
    const uint2* __restrict__ Pp = g_pred + b * PK_PLANE;
    const uint2* __restrict__ Pt = g_true + b * PK_PLANE;

    float pxp = (float)x, pyp = (float)y;   // pred trajectory
    float pxt = (float)x, pyt = (float)y;   // true trajectory
    float acc = 0.0f;

    #pragma unroll
    for (int s = 0; s < NSTEPS; s++) {
        float2 vp = bsample(Pp, pxp, pyp);
        float2 vt = bsample(Pt, pxt, pyt);
        pxp = fmaf(DXC, vp.x, pxp);
        pyp = fmaf(DXC, vp.y, pyp);
        pxt = fmaf(DXC, vt.x, pxt);
        pyt = fmaf(DXC, vt.y, pyt);
        float dx = pxt - pxp;
        float dy = pyt - pyp;
        acc = fmaf(dx, dx, acc);
        acc = fmaf(dy, dy, acc);
    }

    // block reduction: warp shuffle -> shared -> warp0 -> atomicAdd(double)
    float v = acc;
    #pragma unroll
    for (int o = 16; o > 0; o >>= 1)
        v += __shfl_down_sync(0xffffffffu, v, o);

    __shared__ float sred[8];
    int lane = tid & 31;
    int wid  = tid >> 5;
    if (lane == 0) sred[wid] = v;
    __syncthreads();
    if (wid == 0) {
        v = (lane < 8) ? sred[lane] : 0.0f;
        #pragma unroll
        for (int o = 4; o > 0; o >>= 1)
            v += __shfl_down_sync(0xffffffffu, v, o);
        if (lane == 0) atomicAdd(&g_acc, (double)v);
    }
}

__global__ void finalize_kernel(float* __restrict__ out) {
    const double cnt = (double)(NSTEPS + 1) * Bv * 2 * Hv * Wv;  // 84934656
    *out = (float)(g_acc / cnt);
}

extern "C" void kernel_launch(void* const* d_in, const int* in_sizes, int n_in,
                              void* d_out, int out_size) {
    const float* vf_pred = (const float*)d_in[0];
    const float* vf_true = (const float*)d_in[1];
    float* out = (float*)d_out;

    int rp_blocks = (PK_TOTAL + 255) / 256;
    repack_kernel<<<rp_blocks, 256>>>(vf_pred, vf_true);

    dim3 grid(Wv / 8, Hv / 32, Bv);
    traj_kernel<<<grid, 256>>>();

    finalize_kernel<<<1, 1>>>(out);
}

// round 16
// speedup vs baseline: 1.3764x; 1.0147x over previous
#include <cuda_runtime.h>
#include <cuda_fp16.h>

// IVPLoss: 8-step Euler trajectories of bilinear-sampled vector fields,
// MSE between pred and true trajectories (incl. identity step 0).
//
// R16 = R15 (best: 114.8us) + repack MLP:
//  each repack thread packs TWO elements from opposite halves of the
//  buffer (idx, idx + PK_TOTAL/2): independent load groups double
//  per-thread MLP (repack was latency-limited: issue 40%, DRAM 55%),
//  while stores stay lane-coalesced at BOTH sites (the R4 failure was
//  per-thread-CONSECUTIVE elements shredding store wavefronts).
//  traj: R15 8x4 warp tile, fp16 dup-pair, padded row+col (closed ~88us).
//
// Packed layout per pixel (8B): { half2(c0[x],c1[x]), half2(c0[x+1],c1[x+1]) }
// -> one bilinear sample = 2 LDG.64 + HFMA2 lerps, no y+1 clamp.

#define Bv 8
#define Hv 768
#define Wv 768
#define WPK 769                      // padded width  (col 768 = col 767)
#define HPK 769                      // padded height (row 768 = row 767)
#define NSTEPS 8
#define DXC 0.5f

#define PLANE (Hv * Wv)              // 589824
#define PK_PLANE (HPK * WPK)         // 591361
#define PK_TOTAL (Bv * PK_PLANE)     // 4730888
#define PK_HALF (PK_TOTAL / 2)       // 2365444

__device__ uint2 g_pred[PK_TOTAL];
__device__ uint2 g_true[PK_TOTAL];
__device__ double g_acc;

__device__ __forceinline__ unsigned int h2u(__half2 h) {
    return *reinterpret_cast<unsigned int*>(&h);
}

__device__ __forceinline__ uint2 pack_pair(const float* __restrict__ f,
                                           int base, int xs, int x1) {
    __half2 p0 = __floats2half2_rn(__ldg(f + base + xs),
                                   __ldg(f + base + PLANE + xs));
    __half2 p1 = __floats2half2_rn(__ldg(f + base + x1),
                                   __ldg(f + base + PLANE + x1));
    return make_uint2(h2u(p0), h2u(p1));
}

__device__ __forceinline__ void repack_one(const float* __restrict__ pred,
                                           const float* __restrict__ tru,
                                           int idx) {
    int x = idx % WPK;
    int rest = idx / WPK;
    int y = rest % HPK;
    int b = rest / HPK;
    int xs = min(x, Wv - 1);                 // padded col duplicates last col
    int x1 = min(xs + 1, Wv - 1);
    int ys = min(y, Hv - 1);                 // padded row duplicates last row
    int base = b * 2 * PLANE + ys * Wv;      // channel-0 row base
    g_pred[idx] = pack_pair(pred, base, xs, x1);
    g_true[idx] = pack_pair(tru,  base, xs, x1);
}

// two far-apart elements per thread: independent load chains (2x MLP),
// lane-coalesced stores at both sites
__global__ __launch_bounds__(256) void repack_kernel(const float* __restrict__ pred,
                                                     const float* __restrict__ tru) {
    int idx = blockIdx.x * blockDim.x + threadIdx.x;
    if (idx == 0) g_acc = 0.0;
    if (idx >= PK_HALF) return;
    repack_one(pred, tru, idx);
    repack_one(pred, tru, idx + PK_HALF);
}

__device__ __forceinline__ float2 bsample(const uint2* __restrict__ P,
                                          float x, float y) {
    // clip to [0, W-1] / [0, H-1] (matches jnp.clip)
    x = fminf(fmaxf(x, 0.0f), (float)(Wv - 1));
    y = fminf(fmaxf(y, 0.0f), (float)(Hv - 1));
    float xf = floorf(x);
    float yf = floorf(y);
    int xi = (int)xf;
    int yi = (int)yf;
    __half2 wx2 = __float2half2_rn(x - xf);
    __half2 wy2 = __float2half2_rn(y - yf);

    int ofs = yi * WPK + xi;
    uint2 r0 = __ldg(P + ofs);
    uint2 r1 = __ldg(P + ofs + WPK);    // padded bottom row: always valid
    __half2 v00 = *reinterpret_cast<__half2*>(&r0.x);
    __half2 v01 = *reinterpret_cast<__half2*>(&r0.y);
    __half2 v10 = *reinterpret_cast<__half2*>(&r1.x);
    __half2 v11 = *reinterpret_cast<__half2*>(&r1.y);

    __half2 top = __hfma2(wx2, __hsub2(v01, v00), v00);
    __half2 bot = __hfma2(wx2, __hsub2(v11, v10), v10);
    __half2 res = __hfma2(wy2, __hsub2(bot, top), top);
    return __half22float2(res);
}

// grid (96, 24, 8), block 256: warp = 8x4 pixel tile, block = 8x32 tile
__global__ __launch_bounds__(256) void traj_kernel() {
    int tid = threadIdx.x;
    int x = blockIdx.x * 8  + (tid & 7);   // 0..767
    int y = blockIdx.y * 32 + (tid >> 3);  // 0..767
    int b = blockIdx.z;
    const uint2* __restrict__ Pp = g_pred + b * PK_PLANE;
    const uint2* __restrict__ Pt = g_true + b * PK_PLANE;

    float pxp = (float)x, pyp = (float)y;   // pred trajectory
    float pxt = (float)x, pyt = (float)y;   // true trajectory
    float acc = 0.0f;

    #pragma unroll
    for (int s = 0; s < NSTEPS; s++) {
        float2 vp = bsample(Pp, pxp, pyp);
        float2 vt = bsample(Pt, pxt, pyt);
        pxp = fmaf(DXC, vp.x, pxp);
        pyp = fmaf(DXC, vp.y, pyp);
        pxt = fmaf(DXC, vt.x, pxt);
        pyt = fmaf(DXC, vt.y, pyt);
        float dx = pxt - pxp;
        float dy = pyt - pyp;
        acc = fmaf(dx, dx, acc);
        acc = fmaf(dy, dy, acc);
    }

    // block reduction: warp shuffle -> shared -> warp0 -> atomicAdd(double)
    float v = acc;
    #pragma unroll
    for (int o = 16; o > 0; o >>= 1)
        v += __shfl_down_sync(0xffffffffu, v, o);

    __shared__ float sred[8];
    int lane = tid & 31;
    int wid  = tid >> 5;
    if (lane == 0) sred[wid] = v;
    __syncthreads();
    if (wid == 0) {
        v = (lane < 8) ? sred[lane] : 0.0f;
        #pragma unroll
        for (int o = 4; o > 0; o >>= 1)
            v += __shfl_down_sync(0xffffffffu, v, o);
        if (lane == 0) atomicAdd(&g_acc, (double)v);
    }
}

__global__ void finalize_kernel(float* __restrict__ out) {
    const double cnt = (double)(NSTEPS + 1) * Bv * 2 * Hv * Wv;  // 84934656
    *out = (float)(g_acc / cnt);
}

extern "C" void kernel_launch(void* const* d_in, const int* in_sizes, int n_in,
                              void* d_out, int out_size) {
    const float* vf_pred = (const float*)d_in[0];
    const float* vf_true = (const float*)d_in[1];
    float* out = (float*)d_out;

    int rp_blocks = (PK_HALF + 255) / 256;
    repack_kernel<<<rp_blocks, 256>>>(vf_pred, vf_true);

    dim3 grid(Wv / 8, Hv / 32, Bv);
    traj_kernel<<<grid, 256>>>();

    finalize_kernel<<<1, 1>>>(out);
}

// round 17
// speedup vs baseline: 1.3815x; 1.0037x over previous
#include <cuda_runtime.h>
#include <cuda_fp16.h>

// IVPLoss: 8-step Euler trajectories of bilinear-sampled vector fields,
// MSE between pred and true trajectories (incl. identity step 0).
//
// R17 = R16 (best: 113.2us) minus the finalize launch:
//  - repack thread 0 zeroes *out (stream-ordered before traj);
//  - traj blocks atomicAdd(out, partial * (1/cnt)) in float directly
//    (constant folded; float atomic random-walk error ~L*8e-6 << gate).
//  No fence, no counter, no last-block election (the R3 failure mode).
//  repack: 2 far-apart elements/thread (MLP), closed at ~24us.
//  traj: 8x4 warp tile, fp16 dup-pair, padded row+col, closed at ~86us.
//
// Packed layout per pixel (8B): { half2(c0[x],c1[x]), half2(c0[x+1],c1[x+1]) }
// -> one bilinear sample = 2 LDG.64 + HFMA2 lerps, no y+1 clamp.

#define Bv 8
#define Hv 768
#define Wv 768
#define WPK 769                      // padded width  (col 768 = col 767)
#define HPK 769                      // padded height (row 768 = row 767)
#define NSTEPS 8
#define DXC 0.5f

#define PLANE (Hv * Wv)              // 589824
#define PK_PLANE (HPK * WPK)         // 591361
#define PK_TOTAL (Bv * PK_PLANE)     // 4730888
#define PK_HALF (PK_TOTAL / 2)       // 2365444

// 1 / ((NSTEPS+1) * Bv * 2 * Hv * Wv) = 1 / 84934656
#define INV_CNT (1.0f / 84934656.0f)

__device__ uint2 g_pred[PK_TOTAL];
__device__ uint2 g_true[PK_TOTAL];

__device__ __forceinline__ unsigned int h2u(__half2 h) {
    return *reinterpret_cast<unsigned int*>(&h);
}

__device__ __forceinline__ uint2 pack_pair(const float* __restrict__ f,
                                           int base, int xs, int x1) {
    __half2 p0 = __floats2half2_rn(__ldg(f + base + xs),
                                   __ldg(f + base + PLANE + xs));
    __half2 p1 = __floats2half2_rn(__ldg(f + base + x1),
                                   __ldg(f + base + PLANE + x1));
    return make_uint2(h2u(p0), h2u(p1));
}

__device__ __forceinline__ void repack_one(const float* __restrict__ pred,
                                           const float* __restrict__ tru,
                                           int idx) {
    int x = idx % WPK;
    int rest = idx / WPK;
    int y = rest % HPK;
    int b = rest / HPK;
    int xs = min(x, Wv - 1);                 // padded col duplicates last col
    int x1 = min(xs + 1, Wv - 1);
    int ys = min(y, Hv - 1);                 // padded row duplicates last row
    int base = b * 2 * PLANE + ys * Wv;      // channel-0 row base
    g_pred[idx] = pack_pair(pred, base, xs, x1);
    g_true[idx] = pack_pair(tru,  base, xs, x1);
}

// two far-apart elements per thread: independent load chains (2x MLP),
// lane-coalesced stores at both sites. Thread 0 zeroes the output scalar.
__global__ __launch_bounds__(256) void repack_kernel(const float* __restrict__ pred,
                                                     const float* __restrict__ tru,
                                                     float* __restrict__ out) {
    int idx = blockIdx.x * blockDim.x + threadIdx.x;
    if (idx == 0) *out = 0.0f;
    if (idx >= PK_HALF) return;
    repack_one(pred, tru, idx);
    repack_one(pred, tru, idx + PK_HALF);
}

__device__ __forceinline__ float2 bsample(const uint2* __restrict__ P,
                                          float x, float y) {
    // clip to [0, W-1] / [0, H-1] (matches jnp.clip)
    x = fminf(fmaxf(x, 0.0f), (float)(Wv - 1));
    y = fminf(fmaxf(y, 0.0f), (float)(Hv - 1));
    float xf = floorf(x);
    float yf = floorf(y);
    int xi = (int)xf;
    int yi = (int)yf;
    __half2 wx2 = __float2half2_rn(x - xf);
    __half2 wy2 = __float2half2_rn(y - yf);

    int ofs = yi * WPK + xi;
    uint2 r0 = __ldg(P + ofs);
    uint2 r1 = __ldg(P + ofs + WPK);    // padded bottom row: always valid
    __half2 v00 = *reinterpret_cast<__half2*>(&r0.x);
    __half2 v01 = *reinterpret_cast<__half2*>(&r0.y);
    __half2 v10 = *reinterpret_cast<__half2*>(&r1.x);
    __half2 v11 = *reinterpret_cast<__half2*>(&r1.y);

    __half2 top = __hfma2(wx2, __hsub2(v01, v00), v00);
    __half2 bot = __hfma2(wx2, __hsub2(v11, v10), v10);
    __half2 res = __hfma2(wy2, __hsub2(bot, top), top);
    return __half22float2(res);
}

// grid (96, 24, 8), block 256: warp = 8x4 pixel tile, block = 8x32 tile
__global__ __launch_bounds__(256) void traj_kernel(float* __restrict__ out) {
    int tid = threadIdx.x;
    int x = blockIdx.x * 8  + (tid & 7);   // 0..767
    int y = blockIdx.y * 32 + (tid >> 3);  // 0..767
    int b = blockIdx.z;
    const uint2* __restrict__ Pp = g_pred + b * PK_PLANE;
    const uint2* __restrict__ Pt = g_true + b * PK_PLANE;

    float pxp = (float)x, pyp = (float)y;   // pred trajectory
    float pxt = (float)x, pyt = (float)y;   // true trajectory
    float acc = 0.0f;

    #pragma unroll
    for (int s = 0; s < NSTEPS; s++) {
        float2 vp = bsample(Pp, pxp, pyp);
        float2 vt = bsample(Pt, pxt, pyt);
        pxp = fmaf(DXC, vp.x, pxp);
        pyp = fmaf(DXC, vp.y, pyp);
        pxt = fmaf(DXC, vt.x, pxt);
        pyt = fmaf(DXC, vt.y, pyt);
        float dx = pxt - pxp;
        float dy = pyt - pyp;
        acc = fmaf(dx, dx, acc);
        acc = fmaf(dy, dy, acc);
    }

    // block reduction: warp shuffle -> shared -> warp0 -> atomicAdd(out)
    float v = acc;
    #pragma unroll
    for (int o = 16; o > 0; o >>= 1)
        v += __shfl_down_sync(0xffffffffu, v, o);

    __shared__ float sred[8];
    int lane = tid & 31;
    int wid  = tid >> 5;
    if (lane == 0) sred[wid] = v;
    __syncthreads();
    if (wid == 0) {
        v = (lane < 8) ? sred[lane] : 0.0f;
        #pragma unroll
        for (int o = 4; o > 0; o >>= 1)
            v += __shfl_down_sync(0xffffffffu, v, o);
        if (lane == 0) atomicAdd(out, v * INV_CNT);
    }
}

extern "C" void kernel_launch(void* const* d_in, const int* in_sizes, int n_in,
                              void* d_out, int out_size) {
    const float* vf_pred = (const float*)d_in[0];
    const float* vf_true = (const float*)d_in[1];
    float* out = (float*)d_out;

    int rp_blocks = (PK_HALF + 255) / 256;
    repack_kernel<<<rp_blocks, 256>>>(vf_pred, vf_true, out);

    dim3 grid(Wv / 8, Hv / 32, Bv);
    traj_kernel<<<grid, 256>>>(out);
}